// round 2
// baseline (speedup 1.0000x reference)
#include <cuda_runtime.h>
#include <cstdint>
#include <math.h>

#define BB 64
#define HH 256
#define WW 256
#define HWSZ 65536           // H*W
#define NTOT 4194304         // B*H*W

// Output layout (concatenated, reference return order):
#define OFF_UIFFT 0
#define OFF_ABS   8388608
#define OFF_MASK  12582912
#define OFF_FFT   16777216
#define OFF_UK    25165824

__device__ double g_partial[256];
__device__ float  g_r, g_beta;
__device__ int    g_le;
__device__ float2 g_tw[128];   // exp(-i*pi*k/128)

// ---------------- Threefry-2x32-20 (exact jax) ----------------
__host__ __device__ __forceinline__ unsigned rotl32(unsigned v, int d) {
    return (v << d) | (v >> (32 - d));
}

__host__ __device__ inline void threefry2x32(unsigned k0, unsigned k1,
                                             unsigned c0, unsigned c1,
                                             unsigned& o0, unsigned& o1) {
    unsigned ks2 = k0 ^ k1 ^ 0x1BD11BDAu;
    unsigned x0 = c0 + k0;
    unsigned x1 = c1 + k1;
#define TF_R(r) { x0 += x1; x1 = rotl32(x1, r); x1 ^= x0; }
    TF_R(13) TF_R(15) TF_R(26) TF_R(6)
    x0 += k1;  x1 += ks2 + 1u;
    TF_R(17) TF_R(29) TF_R(16) TF_R(24)
    x0 += ks2; x1 += k0 + 2u;
    TF_R(13) TF_R(15) TF_R(26) TF_R(6)
    x0 += k0;  x1 += k1 + 3u;
    TF_R(17) TF_R(29) TF_R(16) TF_R(24)
    x0 += k1;  x1 += ks2 + 4u;
    TF_R(13) TF_R(15) TF_R(26) TF_R(6)
    x0 += ks2; x1 += k0 + 5u;
#undef TF_R
    o0 = x0; o1 = x1;
}

// ---------------- XLA-exact sigmoid pieces ----------------
__device__ __forceinline__ float tanh_xla(float x) {
    float ax = fabsf(x);
    float xc = fminf(fmaxf(x, -7.90531110763549805f), 7.90531110763549805f);
    float x2 = __fmul_rn(xc, xc);
    float p = -2.76076847742355e-16f;
    p = fmaf(p, x2, 2.00018790482477e-13f);
    p = fmaf(p, x2, -8.60467152213735e-11f);
    p = fmaf(p, x2, 5.12229709037114e-08f);
    p = fmaf(p, x2, 1.48572235717979e-05f);
    p = fmaf(p, x2, 6.37261928875436e-04f);
    p = fmaf(p, x2, 4.89352455891786e-03f);
    p = __fmul_rn(p, xc);
    float q = 1.19825839466702e-06f;
    q = fmaf(q, x2, 1.18534705686654e-04f);
    q = fmaf(q, x2, 2.26843463243900e-03f);
    q = fmaf(q, x2, 4.89352518554385e-03f);
    float r = __fdiv_rn(p, q);
    return (ax < 0.0004f) ? x : r;
}

__device__ __forceinline__ float prob1_of(float wv) {
    float arg = __fmul_rn(0.5f, __fmul_rn(5.0f, wv));
    float t = tanh_xla(arg);
    return __fadd_rn(0.5f, __fmul_rn(0.5f, t));
}

// ---------------- twiddle table init ----------------
__global__ void k_twinit() {
    int k = threadIdx.x;
    float s, c;
    sincospif((float)k / 128.0f, &s, &c);
    g_tw[k] = make_float2(c, -s);
}

// ---------------- reduction: xbar = mean(prob1) over H*W ----------------
__global__ void k_reduce(const float* __restrict__ w) {
    __shared__ double sd[256];
    int t = threadIdx.x;
    int idx = blockIdx.x * 256 + t;
    sd[t] = (double)prob1_of(w[idx]);
    __syncthreads();
    for (int s = 128; s > 0; s >>= 1) {
        if (t < s) sd[t] += sd[t + s];
        __syncthreads();
    }
    if (t == 0) g_partial[blockIdx.x] = sd[0];
}

__global__ void k_final() {
    __shared__ double sd[256];
    int t = threadIdx.x;
    sd[t] = g_partial[t];
    __syncthreads();
    for (int s = 128; s > 0; s >>= 1) {
        if (t < s) sd[t] += sd[t + s];
        __syncthreads();
    }
    if (t == 0) {
        float xbar = (float)(sd[0] / 65536.0);
        g_r    = __fdiv_rn(0.125f, xbar);
        g_beta = __fdiv_rn(0.875f, __fsub_rn(1.0f, xbar));
        g_le   = (g_r < 1.0f) ? 1 : 0;
    }
}

// ---------------- mask generation (float4) ----------------
__global__ void k_mask(const float* __restrict__ w, float* __restrict__ mask,
                       unsigned sk0, unsigned sk1) {
    unsigned t = blockIdx.x * 256u + threadIdx.x;
    unsigned i0 = t * 4u;
    float4 wq = *reinterpret_cast<const float4*>(w + (i0 & (HWSZ - 1)));
    float pv[4] = {wq.x, wq.y, wq.z, wq.w};
    float res[4];
    float rr = g_r, bb = g_beta;
    int le = g_le;
#pragma unroll
    for (int j = 0; j < 4; j++) {
        float p1 = prob1_of(pv[j]);
        float prob2 = le ? __fmul_rn(p1, rr)
                         : __fsub_rn(1.0f, __fmul_rn(__fsub_rn(1.0f, p1), bb));
        unsigned o0, o1;
        threefry2x32(sk0, sk1, 0u, i0 + (unsigned)j, o0, o1);
        unsigned bits = o0 ^ o1;
        float u = __uint_as_float((bits >> 9) | 0x3f800000u) - 1.0f;
        res[j] = (prob2 > u) ? 1.0f : 0.0f;
    }
    *reinterpret_cast<float4*>(mask + i0) = make_float4(res[0], res[1], res[2], res[3]);
}

// ---------------- register warp FFT (256-pt, 8 regs x 32 lanes) ----------
__device__ __constant__ int BREV3[8] = {0, 4, 2, 6, 1, 5, 3, 7};
#define SWZ(row) ((row) ^ ((row) >> 5))
#define HSQ 0.70710678118654752f

template<int SIGN>   // -1 fwd, +1 inv
__device__ __forceinline__ void wfft(float (&vr)[8], float (&vi)[8], int lane) {
    // stage 1 (w = 1)
#pragma unroll
    for (int a = 0; a < 8; a += 2) {
        float tr = vr[a + 1], ti = vi[a + 1];
        vr[a + 1] = vr[a] - tr; vi[a + 1] = vi[a] - ti;
        vr[a] += tr; vi[a] += ti;
    }
    // stage 2
#pragma unroll
    for (int a0 = 0; a0 < 8; a0 += 4) {
        { int a = a0, b = a0 + 2;
          float tr = vr[b], ti = vi[b];
          vr[b] = vr[a] - tr; vi[b] = vi[a] - ti; vr[a] += tr; vi[a] += ti; }
        { int a = a0 + 1, b = a0 + 3;   // w = (0, SIGN)
          float tr = (SIGN > 0) ? -vi[b] : vi[b];
          float ti = (SIGN > 0) ?  vr[b] : -vr[b];
          vr[b] = vr[a] - tr; vi[b] = vi[a] - ti; vr[a] += tr; vi[a] += ti; }
    }
    // stage 3: pairs (a, a+4), w = exp(SIGN*i*pi*a/4)
    {
        { int a = 0, b = 4;
          float tr = vr[b], ti = vi[b];
          vr[b] = vr[a] - tr; vi[b] = vi[a] - ti; vr[a] += tr; vi[a] += ti; }
        { int a = 1, b = 5;   // w = (H, SIGN*H)
          float xr = vr[b], xi = vi[b];
          float tr = HSQ * (SIGN > 0 ? (xr - xi) : (xr + xi));
          float ti = HSQ * (SIGN > 0 ? (xi + xr) : (xi - xr));
          vr[b] = vr[a] - tr; vi[b] = vi[a] - ti; vr[a] += tr; vi[a] += ti; }
        { int a = 2, b = 6;   // w = (0, SIGN)
          float xr = vr[b], xi = vi[b];
          float tr = (SIGN > 0) ? -xi : xi;
          float ti = (SIGN > 0) ?  xr : -xr;
          vr[b] = vr[a] - tr; vi[b] = vi[a] - ti; vr[a] += tr; vi[a] += ti; }
        { int a = 3, b = 7;   // w = (-H, SIGN*H)
          float xr = vr[b], xi = vi[b];
          float tr = -HSQ * (SIGN > 0 ? (xr + xi) : (xr - xi));
          float ti =  HSQ * (SIGN > 0 ? (xr - xi) : -(xr + xi));
          vr[b] = vr[a] - tr; vi[b] = vi[a] - ti; vr[a] += tr; vi[a] += ti; }
    }
    // stages 4..8: lane-shuffle butterflies
#pragma unroll
    for (int b = 0; b < 5; b++) {
        int M = 1 << b;
        bool hi = (lane & M) != 0;
        int lp = (lane & (M - 1)) * 8;
#pragma unroll
        for (int r = 0; r < 8; r++) {
            int idx = (lp + r) << (4 - b);
            float2 tw = g_tw[idx];
            float wr = tw.x;
            float wi = (SIGN < 0) ? tw.y : -tw.y;
            float pvr = __shfl_xor_sync(0xffffffffu, vr[r], M);
            float pvi = __shfl_xor_sync(0xffffffffu, vi[r], M);
            float br_ = hi ? vr[r] : pvr, bi_ = hi ? vi[r] : pvi;
            float ar_ = hi ? pvr : vr[r], ai_ = hi ? pvi : vi[r];
            float tr = wr * br_ - wi * bi_;
            float ti = wr * bi_ + wi * br_;
            vr[r] = hi ? ar_ - tr : ar_ + tr;
            vi[r] = hi ? ai_ - ti : ai_ + ti;
        }
    }
}

// ---------------- row forward FFT: x -> fft staging ----------------
__global__ void k_row_fwd(const float* __restrict__ x, float* __restrict__ fftreg) {
    __shared__ float sr[8][256], si[8][256];
    int t = threadIdx.x, lane = t & 31, w = t >> 5;
    int row = blockIdx.x * 8 + w, b = blockIdx.y;
    int b5 = __brev(lane) >> 27;
    const float* xp = x + (size_t)b * HWSZ + (size_t)row * WW;
    float vr[8], vi[8];
#pragma unroll
    for (int r = 0; r < 8; r++) { vr[r] = xp[BREV3[r] * 32 + b5]; vi[r] = 0.0f; }
    wfft<-1>(vr, vi, lane);
#pragma unroll
    for (int r = 0; r < 8; r++) {
        int p = lane * 8 + r, a = SWZ(p);
        sr[w][a] = vr[r]; si[w][a] = vi[r];
    }
    __syncwarp();
    float* fr = fftreg + (size_t)b * 2 * HWSZ + (size_t)row * WW;
    float* fi = fr + HWSZ;
#pragma unroll
    for (int k = 0; k < 8; k++) {
        int p = k * 32 + lane, a = SWZ(p);
        fr[p] = sr[w][a]; fi[p] = si[w][a];
    }
}

// ---------- fused column kernel: col-FFT fwd, mask mult, col-FFT inv ----------
#define CP 257
__global__ void k_col(float* __restrict__ fftreg, const float* __restrict__ mask,
                      float* __restrict__ ukreg, float* __restrict__ stage) {
    __shared__ float sre[16 * CP], sim[16 * CP];
    int t = threadIdx.x, lane = t & 31, w = t >> 5;
    int b = blockIdx.y, c0 = blockIdx.x * 16;
    int c = t & 15, rr = t >> 4;
    int b5 = __brev(lane) >> 27;
    float* fr = fftreg + (size_t)b * 2 * HWSZ;
    float* fi = fr + HWSZ;

    // phase 1: coalesced load
#pragma unroll
    for (int k = 0; k < 16; k++) {
        int row = k * 16 + rr;
        int a = c * CP + SWZ(row);
        int g = row * WW + c0 + c;
        sre[a] = fr[g]; sim[a] = fi[g];
    }
    __syncthreads();

    // phase 3: forward column FFTs (2 per warp)
#pragma unroll
    for (int cc2 = 0; cc2 < 2; cc2++) {
        int cc = w * 2 + cc2;
        float vr[8], vi[8];
#pragma unroll
        for (int r = 0; r < 8; r++) {
            int ri = BREV3[r] * 32 + b5;
            int a = cc * CP + SWZ(ri);
            vr[r] = sre[a]; vi[r] = sim[a];
        }
        __syncwarp();
        wfft<-1>(vr, vi, lane);
#pragma unroll
        for (int r = 0; r < 8; r++) {
            int p = lane * 8 + r;
            int a = cc * CP + SWZ(p);
            sre[a] = vr[r]; sim[a] = vi[r];
        }
        __syncwarp();
    }
    __syncthreads();

    // phase 5: write fft out, compute u_k = fft*mask, write u_k, stash in smem
    const float* mb = mask + (size_t)b * HWSZ;
    float* ur = ukreg + (size_t)b * 2 * HWSZ;
    float* ui = ur + HWSZ;
#pragma unroll
    for (int k = 0; k < 16; k++) {
        int row = k * 16 + rr;
        int g = row * WW + c0 + c;
        int a = c * CP + SWZ(row);
        float xr = sre[a], xi = sim[a];
        fr[g] = xr; fi[g] = xi;
        float m = mb[g];
        float kr = xr * m, ki = xi * m;
        ur[g] = kr; ui[g] = ki;
        sre[a] = kr; sim[a] = ki;
    }
    __syncthreads();

    // phase 7: inverse column FFTs (2 per warp), scale by 1/256
#pragma unroll
    for (int cc2 = 0; cc2 < 2; cc2++) {
        int cc = w * 2 + cc2;
        float vr[8], vi[8];
#pragma unroll
        for (int r = 0; r < 8; r++) {
            int ri = BREV3[r] * 32 + b5;
            int a = cc * CP + SWZ(ri);
            vr[r] = sre[a]; vi[r] = sim[a];
        }
        __syncwarp();
        wfft<1>(vr, vi, lane);
        const float sc = 1.0f / 256.0f;
#pragma unroll
        for (int r = 0; r < 8; r++) {
            int p = lane * 8 + r;
            int a = cc * CP + SWZ(p);
            sre[a] = vr[r] * sc; sim[a] = vi[r] * sc;
        }
        __syncwarp();
    }
    __syncthreads();

    // phase 9: coalesced write to staging (uifft region)
    float* dr = stage + (size_t)b * 2 * HWSZ;
    float* di = dr + HWSZ;
#pragma unroll
    for (int k = 0; k < 16; k++) {
        int row = k * 16 + rr;
        int g = row * WW + c0 + c;
        int a = c * CP + SWZ(row);
        dr[g] = sre[a]; di[g] = sim[a];
    }
}

// ---------- row inverse FFT (in place on uifft) + complex abs ----------
__global__ void k_row_inv(float* __restrict__ uifft, float* __restrict__ cabs) {
    __shared__ float sr[8][256], si[8][256];
    int t = threadIdx.x, lane = t & 31, w = t >> 5;
    int row = blockIdx.x * 8 + w, b = blockIdx.y;
    int b5 = __brev(lane) >> 27;
    float* fr = uifft + (size_t)b * 2 * HWSZ + (size_t)row * WW;
    float* fi = fr + HWSZ;
    float vr[8], vi[8];
#pragma unroll
    for (int r = 0; r < 8; r++) {
        int p = BREV3[r] * 32 + b5;
        vr[r] = fr[p]; vi[r] = fi[p];
    }
    wfft<1>(vr, vi, lane);
    const float sc = 1.0f / 256.0f;
#pragma unroll
    for (int r = 0; r < 8; r++) {
        int p = lane * 8 + r, a = SWZ(p);
        sr[w][a] = vr[r] * sc; si[w][a] = vi[r] * sc;
    }
    __syncwarp();
    float* ap = cabs + (size_t)b * HWSZ + (size_t)row * WW;
#pragma unroll
    for (int k = 0; k < 8; k++) {
        int p = k * 32 + lane, a = SWZ(p);
        float xr = sr[w][a], xi = si[w][a];
        fr[p] = xr; fi[p] = xi;
        ap[p] = sqrtf(xr * xr + xi * xi);
    }
}

extern "C" void kernel_launch(void* const* d_in, const int* in_sizes, int n_in,
                              void* d_out, int out_size) {
    const float* x = (const float*)d_in[0];
    const float* w = (const float*)d_in[1];
    if (n_in >= 2 && in_sizes[0] == HWSZ) {
        x = (const float*)d_in[1];
        w = (const float*)d_in[0];
    }
    float* out   = (float*)d_out;
    float* uifft = out + OFF_UIFFT;
    float* cabs  = out + OFF_ABS;
    float* mask  = out + OFF_MASK;
    float* fft   = out + OFF_FFT;
    float* uk    = out + OFF_UK;

    unsigned sk0, sk1;
    threefry2x32(0u, 42u, 0u, 1u, sk0, sk1);

    k_twinit<<<1, 128>>>();
    k_reduce<<<256, 256>>>(w);
    k_final<<<1, 256>>>();
    k_mask<<<NTOT / 1024, 256>>>(w, mask, sk0, sk1);
    k_row_fwd<<<dim3(HH / 8, BB), 256>>>(x, fft);
    k_col<<<dim3(WW / 16, BB), 256>>>(fft, mask, uk, uifft);
    k_row_inv<<<dim3(HH / 8, BB), 256>>>(uifft, cabs);
}